// round 16
// baseline (speedup 1.0000x reference)
#include <cuda_runtime.h>
#include <math.h>
#include <stdint.h>

#define NFEAT 64
#define DIM   256
#define NHEAD 8
#define HDIM  32

// ---- smem word offsets (u32 words). Total 25984 w = 103,936 B -> 2 CTAs/SM.
//  axf 0..8192        x as bf16 A-fragments (persistent)
//  SB  8192..17408    proj staging ring: 3 bufs x 3072 w (chunk = 4 ksteps)
//  QF  17408 (1024) | KF 18432 (1024) | VF 19456 (1152, stride 36)
//  WA  20608 (4096)   W1 B fragments (staged once per head)
//  ZA  24704 (1024)   z A-fragments (published by scoring warps)
//  RED 25728 (256)
#define SB_W   8192
#define QF_W   17408
#define KF_W   18432
#define VF_W   19456
#define VF_S   36
#define WA_W   20608
#define ZA_W   24704
#define RED_W  25728
#define SMEM_WORDS 25984

// bf16 weight B-fragments, nt-PAIRED as uint4 (prep_kernel each launch)
// WPF: [h 8][ks 16][p 6][lane 32] uint4  -> per head 3072 uint4, chunk j = 768
// W1F: [h 8][nc 2][ks 2][p 8][lane 32] uint4 -> per head 1024 uint4
__device__ __align__(16) uint32_t WPF[8*16*6*32*4];   // 98,304 words
__device__ __align__(16) uint32_t W1F[8*2*2*8*32*4];  // 32,768 words

__device__ __forceinline__ uint32_t pkbf(float lo, float hi) {
    uint32_t r;
    asm("cvt.rn.bf16x2.f32 %0, %1, %2;" : "=r"(r) : "f"(hi), "f"(lo));
    return r;
}
__device__ __forceinline__ void mma_bf16(float4& d,
    uint32_t a0, uint32_t a1, uint32_t a2, uint32_t a3,
    uint32_t b0, uint32_t b1)
{
    asm("mma.sync.aligned.m16n8k16.row.col.f32.bf16.bf16.f32 "
        "{%0,%1,%2,%3}, {%4,%5,%6,%7}, {%8,%9}, {%0,%1,%2,%3};"
        : "+f"(d.x), "+f"(d.y), "+f"(d.z), "+f"(d.w)
        : "r"(a0), "r"(a1), "r"(a2), "r"(a3), "r"(b0), "r"(b1));
}
__device__ __forceinline__ uint32_t s2u(const void* p) {
    uint32_t a;
    asm("{ .reg .u64 t; cvta.to.shared.u64 t, %1; cvt.u32.u64 %0, t; }"
        : "=r"(a) : "l"(p));
    return a;
}
#define CPA16(dst, src) \
    asm volatile("cp.async.cg.shared.global [%0], [%1], 16;" :: "r"(dst), "l"(src))
#define CPCOMMIT() asm volatile("cp.async.commit_group;" ::: "memory")
#define CPWAIT1()  asm volatile("cp.async.wait_group 1;"  ::: "memory")
#define CPWAIT2()  asm volatile("cp.async.wait_group 2;"  ::: "memory")
#define CPWAIT3()  asm volatile("cp.async.wait_group 3;"  ::: "memory")

// ---------------- prep: weights -> paired bf16 B-fragments ----------------
__global__ __launch_bounds__(256)
void prep_kernel(const float* __restrict__ Wq, const float* __restrict__ Wk,
                 const float* __restrict__ Wv, const float* __restrict__ W1)
{
    int id = blockIdx.x * 256 + threadIdx.x;   // 32768 uint4 slots
    if (id < 24576) {                          // WPF: [h][ks][p][lane]
        int lane = id & 31;
        int g    = id >> 5;
        int p    = g % 6;
        int ks   = (g / 6) & 15;
        int h    = g / 96;
        uint4 v;
#pragma unroll
        for (int e = 0; e < 2; e++) {
            int nt  = 2 * p + e;
            int mat = nt >> 2;
            const float* W = (mat == 0) ? Wq : (mat == 1) ? Wk : Wv;
            int n  = h * HDIM + (nt & 3) * 8 + (lane >> 2);
            int k0 = ks * 16 + (lane & 3) * 2;
            uint32_t b0 = pkbf(W[k0 * DIM + n],       W[(k0 + 1) * DIM + n]);
            uint32_t b1 = pkbf(W[(k0 + 8) * DIM + n], W[(k0 + 9) * DIM + n]);
            if (e == 0) { v.x = b0; v.y = b1; } else { v.z = b0; v.w = b1; }
        }
        ((uint4*)WPF)[id] = v;
    } else {                                   // W1F: [h][nc][ks][p][lane]
        int j    = id - 24576;
        int lane = j & 31;
        int g    = j >> 5;
        int p    = g & 7;
        int ks   = (g >> 3) & 1;
        int nc   = (g >> 4) & 1;
        int h    = g >> 5;
        uint4 v;
#pragma unroll
        for (int e = 0; e < 2; e++) {
            int nt = 2 * p + e;
            int n  = nc * 128 + nt * 8 + (lane >> 2);
            int k0 = h * HDIM + ks * 16 + (lane & 3) * 2;
            uint32_t b0 = pkbf(W1[k0 * DIM + n],       W1[(k0 + 1) * DIM + n]);
            uint32_t b1 = pkbf(W1[(k0 + 8) * DIM + n], W1[(k0 + 9) * DIM + n]);
            if (e == 0) { v.x = b0; v.y = b1; } else { v.z = b0; v.w = b1; }
        }
        ((uint4*)W1F)[j] = v;
    }
}

// ---------------- main ----------------
__global__ __launch_bounds__(256, 2)
void autoint_kernel(const float* __restrict__ x,
                    const float* __restrict__ bq, const float* __restrict__ bk,
                    const float* __restrict__ bv, const float* __restrict__ b1,
                    const float* __restrict__ W2, const float* __restrict__ b2,
                    float* __restrict__ out)
{
    extern __shared__ float sm[];
    uint32_t* smw = (uint32_t*)sm;
    float* red = sm + RED_W;
    const uint32_t smu = s2u(sm);

    const int t = threadIdx.x;
    const int b = blockIdx.x;
    const float* xg = x + (size_t)b * (NFEAT * DIM);

    const int lane = t & 31;
    const int grp  = lane >> 2;
    const int tig  = lane & 3;
    const int w    = t >> 5;
    const int mt   = w & 3;
    const int half = w >> 2;
    const float isd = 0.17677669529663687f;   // 1/sqrt(32)

    // ---- phase 0: x -> bf16 A-fragment order ----
    {
        const float4* xg4 = (const float4*)xg;
#pragma unroll
        for (int n = t; n < NFEAT * DIM / 4; n += 256) {
            float4 v = xg4[n];
            int r   = n >> 6;
            int c4  = (n & 63) << 2;
            int rmt = r >> 4, rgr = r & 7, hi8 = (r >> 3) & 1;
            int ks  = c4 >> 4, koff = c4 & 15;
            int hi  = koff >> 3, tg0 = (koff >> 1) & 3;
            int comp = hi8 + (hi << 1);
            uint32_t* d = smw + (((rmt * 16 + ks) * 32 + rgr * 4) << 2) + comp;
            d[tg0 * 4]       = pkbf(v.x, v.y);
            d[(tg0 + 1) * 4] = pkbf(v.z, v.w);
        }
    }

    float4 facc4[16];
#pragma unroll
    for (int i = 0; i < 16; i++) facc4[i] = make_float4(0.f, 0.f, 0.f, 0.f);

    const uint4* wpf4 = (const uint4*)WPF;   // 768 uint4 per chunk (4 ksteps)
    const uint4* w1f4 = (const uint4*)W1F;   // 1024 uint4 per head

    // ---- prologue: prefetch chunks 0 and 1 ----
#pragma unroll
    for (int c = 0; c < 2; c++) {
        const uint4* src = wpf4 + c * 768;
        const uint32_t dofs = SB_W + c * 3072;
#pragma unroll
        for (int i = 0; i < 3; i++)
            CPA16(smu + ((dofs + (t + i * 256) * 4) << 2), src + t + i * 256);
        CPCOMMIT();
    }

    for (int h = 0; h < NHEAD; h++) {
        const int hd = h * HDIM;

        // ===== QKV projection: 4 chunks of 4 ksteps, 3-buffer ring,
        //       prefetch depth 2 rolling across head boundaries =====
        float4 D[6];
#pragma unroll
        for (int i = 0; i < 6; i++) D[i] = make_float4(0.f, 0.f, 0.f, 0.f);

#pragma unroll
        for (int j = 0; j < 4; j++) {
            // wait for chunk c = 4h+j (commit-ladder derived counts)
            if (j == 0 || j == 3) { CPWAIT1(); } else { CPWAIT2(); }
            __syncthreads();   // chunk visible; buf[(c+2)%3] readers done
            const int c  = h * 4 + j;
            const int cp = c + 2;
            if (cp < 32) {     // prefetch chunk c+2 (may belong to head h+1)
                const uint4* src = wpf4 + cp * 768;
                const uint32_t dofs = SB_W + (cp % 3) * 3072;
#pragma unroll
                for (int i = 0; i < 3; i++)
                    CPA16(smu + ((dofs + (t + i * 256) * 4) << 2), src + t + i * 256);
            }
            CPCOMMIT();        // unconditional: keeps group accounting aligned
            if (j == 0) {      // stage W1(h) early (overlaps proj+scores)
                const uint4* s1 = w1f4 + h * 1024;
#pragma unroll
                for (int i = 0; i < 4; i++)
                    CPA16(smu + ((WA_W + (t + i * 256) * 4) << 2), s1 + t + i * 256);
                CPCOMMIT();
            }
            const uint4* bw4 = (const uint4*)(smw + SB_W + (c % 3) * 3072);
#pragma unroll
            for (int ksl = 0; ksl < 4; ksl++) {
                int ks = j * 4 + ksl;
                uint4 av = ((const uint4*)smw)[(mt * 16 + ks) * 32 + lane];
                const uint4* bp = bw4 + (ksl * 6 + half * 3) * 32 + lane;
#pragma unroll
                for (int jj = 0; jj < 3; jj++) {
                    uint4 bb = bp[jj * 32];
                    mma_bf16(D[2*jj],   av.x, av.y, av.z, av.w, bb.x, bb.y);
                    mma_bf16(D[2*jj+1], av.x, av.y, av.z, av.w, bb.z, bb.w);
                }
            }
        }

        // ===== scatter q->A-frags, k/v->B-frags (no sync needed before:
        //       frag regions disjoint from proj reads; prior readers done) ==
        if (half == 0) {
#pragma unroll
            for (int ks = 0; ks < 2; ks++) {
                float4 dA = D[2 * ks];
                float4 dB = D[2 * ks + 1];
                float2 bA = *(const float2*)&bq[hd + ks * 16 + 2 * tig];
                float2 bB = *(const float2*)&bq[hd + ks * 16 + 8 + 2 * tig];
                uint4 qa;
                qa.x = pkbf((dA.x + bA.x) * isd, (dA.y + bA.y) * isd);
                qa.y = pkbf((dA.z + bA.x) * isd, (dA.w + bA.y) * isd);
                qa.z = pkbf((dB.x + bB.x) * isd, (dB.y + bB.y) * isd);
                qa.w = pkbf((dB.z + bB.x) * isd, (dB.w + bB.y) * isd);
                ((uint4*)(smw + QF_W))[(mt * 2 + ks) * 32 + lane] = qa;
            }
#pragma unroll
            for (int nt = 4; nt < 6; nt++) {       // k cols 0..15
                float4 d = D[nt];
                int base = (nt - 4) * 8;
                float2 bb = *(const float2*)&bk[hd + base + 2 * tig];
                int breg = (nt == 5);
                uint32_t* kf = smw + KF_W;
                int i0 = (((0 * 8 + mt * 2) * 32 + grp * 4 + tig) << 1) + breg;
                int i1 = (((0 * 8 + mt * 2 + 1) * 32 + grp * 4 + tig) << 1) + breg;
                kf[i0] = pkbf(d.x + bb.x, d.y + bb.y);
                kf[i1] = pkbf(d.z + bb.x, d.w + bb.y);
            }
        } else {
#pragma unroll
            for (int nt = 0; nt < 2; nt++) {       // k cols 16..31
                float4 d = D[nt];
                int base = 16 + nt * 8;
                float2 bb = *(const float2*)&bk[hd + base + 2 * tig];
                int breg = nt;
                uint32_t* kf = smw + KF_W;
                int i0 = (((1 * 8 + mt * 2) * 32 + grp * 4 + tig) << 1) + breg;
                int i1 = (((1 * 8 + mt * 2 + 1) * 32 + grp * 4 + tig) << 1) + breg;
                kf[i0] = pkbf(d.x + bb.x, d.y + bb.y);
                kf[i1] = pkbf(d.z + bb.x, d.w + bb.y);
            }
            uint32_t* vf = smw + VF_W;
#pragma unroll
            for (int nt = 2; nt < 6; nt++) {       // v cols 0..31
                float4 d = D[nt];
                int d0 = (nt - 2) * 8 + 2 * tig;
                float2 bb = *(const float2*)&bv[hd + d0];
                float vx = d.x + bb.x, vy = d.y + bb.y;
                float vz = d.z + bb.x, vw = d.w + bb.y;
                float px = __shfl_xor_sync(0xFFFFFFFFu, vx, 4);
                float py = __shfl_xor_sync(0xFFFFFFFFu, vy, 4);
                float pz = __shfl_xor_sync(0xFFFFFFFFu, vz, 4);
                float pw = __shfl_xor_sync(0xFFFFFFFFu, vw, 4);
                if (!(grp & 1)) {
                    int r0  = mt * 16 + grp;
                    int j2a = r0 >> 1, j2b = j2a + 4;
                    vf[d0 * VF_S + j2a]       = pkbf(vx, px);
                    vf[(d0 + 1) * VF_S + j2a] = pkbf(vy, py);
                    vf[d0 * VF_S + j2b]       = pkbf(vz, pz);
                    vf[(d0 + 1) * VF_S + j2b] = pkbf(vw, pw);
                }
            }
        }
        __syncthreads();   // QF/KF/VF visible

        // ===== scores + softmax + z: half=0 warps only =====
        if (half == 0) {
            float4 Ds[8];
#pragma unroll
            for (int i = 0; i < 8; i++) Ds[i] = make_float4(0.f, 0.f, 0.f, 0.f);
#pragma unroll
            for (int ks = 0; ks < 2; ks++) {
                uint4 qa = ((const uint4*)(smw + QF_W))[(mt * 2 + ks) * 32 + lane];
#pragma unroll
                for (int nt = 0; nt < 8; nt++) {
                    uint2 kb = ((const uint2*)(smw + KF_W))[(ks * 8 + nt) * 32 + lane];
                    mma_bf16(Ds[nt], qa.x, qa.y, qa.z, qa.w, kb.x, kb.y);
                }
            }
            float m0 = Ds[0].x, m1 = Ds[0].z;
#pragma unroll
            for (int nt = 0; nt < 8; nt++) {
                m0 = fmaxf(m0, fmaxf(Ds[nt].x, Ds[nt].y));
                m1 = fmaxf(m1, fmaxf(Ds[nt].z, Ds[nt].w));
            }
            m0 = fmaxf(m0, __shfl_xor_sync(0xFFFFFFFFu, m0, 1));
            m0 = fmaxf(m0, __shfl_xor_sync(0xFFFFFFFFu, m0, 2));
            m1 = fmaxf(m1, __shfl_xor_sync(0xFFFFFFFFu, m1, 1));
            m1 = fmaxf(m1, __shfl_xor_sync(0xFFFFFFFFu, m1, 2));
            float s0 = 0.f, s1 = 0.f;
#pragma unroll
            for (int nt = 0; nt < 8; nt++) {
                Ds[nt].x = __expf(Ds[nt].x - m0);
                Ds[nt].y = __expf(Ds[nt].y - m0);
                Ds[nt].z = __expf(Ds[nt].z - m1);
                Ds[nt].w = __expf(Ds[nt].w - m1);
                s0 += Ds[nt].x + Ds[nt].y;
                s1 += Ds[nt].z + Ds[nt].w;
            }
            s0 += __shfl_xor_sync(0xFFFFFFFFu, s0, 1);
            s0 += __shfl_xor_sync(0xFFFFFFFFu, s0, 2);
            s1 += __shfl_xor_sync(0xFFFFFFFFu, s1, 1);
            s1 += __shfl_xor_sync(0xFFFFFFFFu, s1, 2);
            const float inv0 = 1.f / s0, inv1 = 1.f / s1;

            float4 Dz[4];
#pragma unroll
            for (int i = 0; i < 4; i++) Dz[i] = make_float4(0.f, 0.f, 0.f, 0.f);
            const uint32_t* vfw = smw + VF_W;
#pragma unroll
            for (int kz = 0; kz < 4; kz++) {
                uint32_t a0 = pkbf(Ds[2*kz].x   * inv0, Ds[2*kz].y   * inv0);
                uint32_t a1 = pkbf(Ds[2*kz].z   * inv1, Ds[2*kz].w   * inv1);
                uint32_t a2 = pkbf(Ds[2*kz+1].x * inv0, Ds[2*kz+1].y * inv0);
                uint32_t a3 = pkbf(Ds[2*kz+1].z * inv1, Ds[2*kz+1].w * inv1);
#pragma unroll
                for (int ntd = 0; ntd < 4; ntd++) {
                    uint32_t b0 = vfw[(ntd * 8 + grp) * VF_S + 8 * kz + tig];
                    uint32_t b1 = vfw[(ntd * 8 + grp) * VF_S + 8 * kz + tig + 4];
                    mma_bf16(Dz[ntd], a0, a1, a2, a3, b0, b1);
                }
            }
            // pack z -> W1 A-frags, publish to ZA
#pragma unroll
            for (int ks = 0; ks < 2; ks++) {
                uint4 za;
                za.x = pkbf(Dz[2*ks].x,   Dz[2*ks].y);
                za.y = pkbf(Dz[2*ks].z,   Dz[2*ks].w);
                za.z = pkbf(Dz[2*ks+1].x, Dz[2*ks+1].y);
                za.w = pkbf(Dz[2*ks+1].z, Dz[2*ks+1].w);
                ((uint4*)(smw + ZA_W))[(mt * 2 + ks) * 32 + lane] = za;
            }
        }
        CPWAIT3();         // W1(h) staged (3 newer proj prefetch groups may pend)
        __syncthreads();   // WA + ZA visible to all

        // ===== facc += z @ W1 (paired B loads) =====
        {
            uint4 za0 = ((const uint4*)(smw + ZA_W))[(mt * 2 + 0) * 32 + lane];
            uint4 za1 = ((const uint4*)(smw + ZA_W))[(mt * 2 + 1) * 32 + lane];
            const uint4* wa4 = (const uint4*)(smw + WA_W);
#pragma unroll
            for (int nc = 0; nc < 2; nc++) {
#pragma unroll
                for (int ks = 0; ks < 2; ks++) {
                    uint4 za = ks ? za1 : za0;
                    const uint4* bp = wa4 + (((nc * 2 + ks) * 8) + half * 4) * 32 + lane;
#pragma unroll
                    for (int jj = 0; jj < 4; jj++) {
                        uint4 bb = bp[jj * 32];
                        mma_bf16(facc4[nc*8 + 2*jj],   za.x, za.y, za.z, za.w, bb.x, bb.y);
                        mma_bf16(facc4[nc*8 + 2*jj+1], za.x, za.y, za.z, za.w, bb.z, bb.w);
                    }
                }
            }
        }
        // next head's j0 sync protects WA/ZA/frag reuse
    }

    // ===== epilogue: f = relu(facc + b1 + x); dot W2 (x exact from gmem) ====
    {
        const int r0 = mt * 16 + grp, r1 = r0 + 8;
        float part = 0.f;
#pragma unroll
        for (int fi = 0; fi < 16; fi++) {
            int nc = fi >> 3, nt = fi & 7;
            int n  = nc * 128 + half * 64 + nt * 8 + 2 * tig;
            float2 b1v = *(const float2*)&b1[n];
            float2 x0  = *(const float2*)&xg[r0 * DIM + n];
            float2 x1  = *(const float2*)&xg[r1 * DIM + n];
            float2 w20 = *(const float2*)&W2[r0 * DIM + n];
            float2 w21 = *(const float2*)&W2[r1 * DIM + n];
            float4 d = facc4[fi];
            float f0 = fmaxf(d.x + b1v.x + x0.x, 0.f);
            float f1 = fmaxf(d.y + b1v.y + x0.y, 0.f);
            float f2 = fmaxf(d.z + b1v.x + x1.x, 0.f);
            float f3 = fmaxf(d.w + b1v.y + x1.y, 0.f);
            part += f0 * w20.x + f1 * w20.y + f2 * w21.x + f3 * w21.y;
        }
        red[t] = part;
    }
    __syncthreads();

#pragma unroll
    for (int s = 128; s > 0; s >>= 1) {
        if (t < s) red[t] += red[t + s];
        __syncthreads();
    }
    if (t == 0) {
        out[b] = 1.f / (1.f + __expf(-(red[0] + b2[0])));
    }
}

extern "C" void kernel_launch(void* const* d_in, const int* in_sizes, int n_in,
                              void* d_out, int out_size)
{
    const float* x  = (const float*)d_in[0];
    const float* Wq = (const float*)d_in[1];
    const float* bq = (const float*)d_in[2];
    const float* Wk = (const float*)d_in[3];
    const float* bk = (const float*)d_in[4];
    const float* Wv = (const float*)d_in[5];
    const float* bv = (const float*)d_in[6];
    const float* W1 = (const float*)d_in[7];
    const float* b1 = (const float*)d_in[8];
    const float* W2 = (const float*)d_in[9];
    const float* b2 = (const float*)d_in[10];
    float* out = (float*)d_out;

    prep_kernel<<<128, 256>>>(Wq, Wk, Wv, W1);

    const int smem_bytes = SMEM_WORDS * 4;   // 103,936 B -> 2 CTAs/SM
    cudaFuncSetAttribute(autoint_kernel,
                         cudaFuncAttributeMaxDynamicSharedMemorySize, smem_bytes);
    autoint_kernel<<<8192, 256, smem_bytes>>>(x, bq, bk, bv, b1, W2, b2, out);
}

// round 17
// speedup vs baseline: 1.0639x; 1.0639x over previous
#include <cuda_runtime.h>
#include <math.h>
#include <stdint.h>

#define NFEAT 64
#define DIM   256
#define NHEAD 8
#define HDIM  32

// ---- smem word offsets (u32 words). Total 23936 w = 95,744 B -> 2 CTAs/SM.
//  AXF 0..8192        x as bf16 A-fragments (persistent)
//  PB0 8192  (6144)   proj chunk buffer (ping-pong c0/c1 by head parity)
//  PB1 14336 (6144)   (WA aliases dead c0-buffer base; ZA at +4096)
//  QF  20480 (1024) | KF 21504 (1024, paired uint4) | VF 22528 (1152)
//  RED 23680 (256)
#define PB0_W  8192
#define PB1_W  14336
#define QF_W   20480
#define KF_W   21504
#define VF_W   22528
#define VF_S   36
#define RED_W  23680
#define SMEM_WORDS 23936

// bf16 weight B-fragments, nt-PAIRED as uint4 (prep_kernel each launch)
// WPF: [h 8][ks 16][p 6][lane 32] uint4  -> 3072 uint4/head; 1536/chunk
// W1F: [h 8][nc 2][ks 2][p 8][lane 32] uint4 -> 1024 uint4/head
__device__ __align__(16) uint32_t WPF[8*16*6*32*4];
__device__ __align__(16) uint32_t W1F[8*2*2*8*32*4];

__device__ __forceinline__ uint32_t pkbf(float lo, float hi) {
    uint32_t r;
    asm("cvt.rn.bf16x2.f32 %0, %1, %2;" : "=r"(r) : "f"(hi), "f"(lo));
    return r;
}
__device__ __forceinline__ void mma_bf16(float4& d,
    uint32_t a0, uint32_t a1, uint32_t a2, uint32_t a3,
    uint32_t b0, uint32_t b1)
{
    asm("mma.sync.aligned.m16n8k16.row.col.f32.bf16.bf16.f32 "
        "{%0,%1,%2,%3}, {%4,%5,%6,%7}, {%8,%9}, {%0,%1,%2,%3};"
        : "+f"(d.x), "+f"(d.y), "+f"(d.z), "+f"(d.w)
        : "r"(a0), "r"(a1), "r"(a2), "r"(a3), "r"(b0), "r"(b1));
}
__device__ __forceinline__ uint32_t s2u(const void* p) {
    uint32_t a;
    asm("{ .reg .u64 t; cvta.to.shared.u64 t, %1; cvt.u32.u64 %0, t; }"
        : "=r"(a) : "l"(p));
    return a;
}
#define CPA16(dst, src) \
    asm volatile("cp.async.cg.shared.global [%0], [%1], 16;" :: "r"(dst), "l"(src))
#define CPCOMMIT() asm volatile("cp.async.commit_group;" ::: "memory")
#define CPWAIT0()  asm volatile("cp.async.wait_group 0;"  ::: "memory")
#define CPWAIT1()  asm volatile("cp.async.wait_group 1;"  ::: "memory")

// ---------------- prep: weights -> paired bf16 B-fragments ----------------
__global__ __launch_bounds__(256)
void prep_kernel(const float* __restrict__ Wq, const float* __restrict__ Wk,
                 const float* __restrict__ Wv, const float* __restrict__ W1)
{
    int id = blockIdx.x * 256 + threadIdx.x;   // 32768 uint4 slots
    if (id < 24576) {                          // WPF: [h][ks][p][lane]
        int lane = id & 31;
        int g    = id >> 5;
        int p    = g % 6;
        int ks   = (g / 6) & 15;
        int h    = g / 96;
        uint4 v;
#pragma unroll
        for (int e = 0; e < 2; e++) {
            int nt  = 2 * p + e;
            int mat = nt >> 2;
            const float* W = (mat == 0) ? Wq : (mat == 1) ? Wk : Wv;
            int n  = h * HDIM + (nt & 3) * 8 + (lane >> 2);
            int k0 = ks * 16 + (lane & 3) * 2;
            uint32_t b0 = pkbf(W[k0 * DIM + n],       W[(k0 + 1) * DIM + n]);
            uint32_t b1 = pkbf(W[(k0 + 8) * DIM + n], W[(k0 + 9) * DIM + n]);
            if (e == 0) { v.x = b0; v.y = b1; } else { v.z = b0; v.w = b1; }
        }
        ((uint4*)WPF)[id] = v;
    } else {                                   // W1F: [h][nc][ks][p][lane]
        int j    = id - 24576;
        int lane = j & 31;
        int g    = j >> 5;
        int p    = g & 7;
        int ks   = (g >> 3) & 1;
        int nc   = (g >> 4) & 1;
        int h    = g >> 5;
        uint4 v;
#pragma unroll
        for (int e = 0; e < 2; e++) {
            int nt = 2 * p + e;
            int n  = nc * 128 + nt * 8 + (lane >> 2);
            int k0 = h * HDIM + ks * 16 + (lane & 3) * 2;
            uint32_t b0 = pkbf(W1[k0 * DIM + n],       W1[(k0 + 1) * DIM + n]);
            uint32_t b1 = pkbf(W1[(k0 + 8) * DIM + n], W1[(k0 + 9) * DIM + n]);
            if (e == 0) { v.x = b0; v.y = b1; } else { v.z = b0; v.w = b1; }
        }
        ((uint4*)W1F)[j] = v;
    }
}

// ---------------- main ----------------
__global__ __launch_bounds__(256, 2)
void autoint_kernel(const float* __restrict__ x,
                    const float* __restrict__ bq, const float* __restrict__ bk,
                    const float* __restrict__ bv, const float* __restrict__ b1,
                    const float* __restrict__ W2, const float* __restrict__ b2,
                    float* __restrict__ out)
{
    extern __shared__ float sm[];
    uint32_t* smw = (uint32_t*)sm;
    float* red = sm + RED_W;
    const uint32_t smu = s2u(sm);

    const int t = threadIdx.x;
    const int b = blockIdx.x;
    const float* xg = x + (size_t)b * (NFEAT * DIM);

    const int lane = t & 31;
    const int grp  = lane >> 2;
    const int tig  = lane & 3;
    const int w    = t >> 5;
    const int mt   = w & 3;
    const int half = w >> 2;
    const float isd = 0.17677669529663687f;   // 1/sqrt(32)

    // ---- phase 0: x -> bf16 A-fragment order ----
    {
        const float4* xg4 = (const float4*)xg;
#pragma unroll
        for (int n = t; n < NFEAT * DIM / 4; n += 256) {
            float4 v = xg4[n];
            int r   = n >> 6;
            int c4  = (n & 63) << 2;
            int rmt = r >> 4, rgr = r & 7, hi8 = (r >> 3) & 1;
            int ks  = c4 >> 4, koff = c4 & 15;
            int hi  = koff >> 3, tg0 = (koff >> 1) & 3;
            int comp = hi8 + (hi << 1);
            uint32_t* d = smw + (((rmt * 16 + ks) * 32 + rgr * 4) << 2) + comp;
            d[tg0 * 4]       = pkbf(v.x, v.y);
            d[(tg0 + 1) * 4] = pkbf(v.z, v.w);
        }
    }

    float4 facc4[16];
#pragma unroll
    for (int i = 0; i < 16; i++) facc4[i] = make_float4(0.f, 0.f, 0.f, 0.f);

    const uint4* wpf4 = (const uint4*)WPF;   // 1536 uint4 per chunk
    const uint4* w1f4 = (const uint4*)W1F;   // 1024 uint4 per head

    // ---- prologue: stage c0(0) -> PB0 (overlaps nothing; waited in-loop) --
    {
        const uint4* src = wpf4;   // h=0, chunk0
#pragma unroll
        for (int i = 0; i < 6; i++)
            CPA16(smu + ((PB0_W + (t + i * 256) * 4) << 2), src + t + i * 256);
        CPCOMMIT();
    }

    for (int h = 0; h < NHEAD; h++) {
        const int hd = h * HDIM;
        const uint32_t c0b = (h & 1) ? PB1_W : PB0_W;
        const uint32_t c1b = (h & 1) ? PB0_W : PB1_W;
        __syncthreads();   // loop-top: W1(h-1) readers done -> c1b writable;
                           // h=0: axf visible

        // stage c1(h) -> c1b
        {
            const uint4* src = wpf4 + h * 3072 + 1536;
#pragma unroll
            for (int i = 0; i < 6; i++)
                CPA16(smu + ((c1b + (t + i * 256) * 4) << 2), src + t + i * 256);
            CPCOMMIT();
        }
        CPWAIT1();         // c0(h) complete (c1 may pend)
        __syncthreads();   // c0 visible to all

        float4 D[6];
#pragma unroll
        for (int i = 0; i < 6; i++) D[i] = make_float4(0.f, 0.f, 0.f, 0.f);

        // ---- chunk0 compute (ks 0..7) ----
        {
            const uint4* bw4 = (const uint4*)(smw + c0b);
#pragma unroll
            for (int ks = 0; ks < 8; ks++) {
                uint4 av = ((const uint4*)smw)[(mt * 16 + ks) * 32 + lane];
                const uint4* bp = bw4 + (ks * 6 + half * 3) * 32 + lane;
#pragma unroll
                for (int jj = 0; jj < 3; jj++) {
                    uint4 bb = bp[jj * 32];
                    mma_bf16(D[2*jj],   av.x, av.y, av.z, av.w, bb.x, bb.y);
                    mma_bf16(D[2*jj+1], av.x, av.y, av.z, av.w, bb.z, bb.w);
                }
            }
        }
        CPWAIT0();         // c1(h) complete
        __syncthreads();   // c1 visible; all warps done reading c0b
        // stage W1(h) into freed c0b (hidden behind chunk1+scatter+scores)
        {
            const uint4* s1 = w1f4 + h * 1024;
#pragma unroll
            for (int i = 0; i < 4; i++)
                CPA16(smu + ((c0b + (t + i * 256) * 4) << 2), s1 + t + i * 256);
            CPCOMMIT();
        }
        // ---- chunk1 compute (ks 8..15) ----
        {
            const uint4* bw4 = (const uint4*)(smw + c1b);
#pragma unroll
            for (int ks = 8; ks < 16; ks++) {
                uint4 av = ((const uint4*)smw)[(mt * 16 + ks) * 32 + lane];
                const uint4* bp = bw4 + ((ks - 8) * 6 + half * 3) * 32 + lane;
#pragma unroll
                for (int jj = 0; jj < 3; jj++) {
                    uint4 bb = bp[jj * 32];
                    mma_bf16(D[2*jj],   av.x, av.y, av.z, av.w, bb.x, bb.y);
                    mma_bf16(D[2*jj+1], av.x, av.y, av.z, av.w, bb.z, bb.w);
                }
            }
        }

        // ---- scatter q->A-frags, k(paired uint4)/v->B-frags ----
        if (half == 0) {
#pragma unroll
            for (int ks = 0; ks < 2; ks++) {
                float4 dA = D[2 * ks];
                float4 dB = D[2 * ks + 1];
                float2 bA = *(const float2*)&bq[hd + ks * 16 + 2 * tig];
                float2 bB = *(const float2*)&bq[hd + ks * 16 + 8 + 2 * tig];
                uint4 qa;
                qa.x = pkbf((dA.x + bA.x) * isd, (dA.y + bA.y) * isd);
                qa.y = pkbf((dA.z + bA.x) * isd, (dA.w + bA.y) * isd);
                qa.z = pkbf((dB.x + bB.x) * isd, (dB.y + bB.y) * isd);
                qa.w = pkbf((dB.z + bB.x) * isd, (dB.w + bB.y) * isd);
                ((uint4*)(smw + QF_W))[(mt * 2 + ks) * 32 + lane] = qa;
            }
            {   // k cols 0..15 (kst 0): D[4]=breg0, D[5]=breg1, one STS.128
                float4 d0 = D[4], d1 = D[5];
                float2 b0 = *(const float2*)&bk[hd + 2 * tig];
                float2 b1v = *(const float2*)&bk[hd + 8 + 2 * tig];
                uint4 kp;
                kp.x = pkbf(d0.x + b0.x,  d0.y + b0.y);   // j0, breg0
                kp.y = pkbf(d1.x + b1v.x, d1.y + b1v.y);  // j0, breg1
                kp.z = pkbf(d0.z + b0.x,  d0.w + b0.y);   // j1, breg0
                kp.w = pkbf(d1.z + b1v.x, d1.w + b1v.y);  // j1, breg1
                ((uint4*)(smw + KF_W))[(0 * 4 + mt) * 32 + lane] = kp;
            }
        } else {
            {   // k cols 16..31 (kst 1): D[0]=breg0, D[1]=breg1
                float4 d0 = D[0], d1 = D[1];
                float2 b0 = *(const float2*)&bk[hd + 16 + 2 * tig];
                float2 b1v = *(const float2*)&bk[hd + 24 + 2 * tig];
                uint4 kp;
                kp.x = pkbf(d0.x + b0.x,  d0.y + b0.y);
                kp.y = pkbf(d1.x + b1v.x, d1.y + b1v.y);
                kp.z = pkbf(d0.z + b0.x,  d0.w + b0.y);
                kp.w = pkbf(d1.z + b1v.x, d1.w + b1v.y);
                ((uint4*)(smw + KF_W))[(1 * 4 + mt) * 32 + lane] = kp;
            }
            uint32_t* vf = smw + VF_W;
#pragma unroll
            for (int nt = 2; nt < 6; nt++) {       // v cols 0..31
                float4 d = D[nt];
                int d0 = (nt - 2) * 8 + 2 * tig;
                float2 bb = *(const float2*)&bv[hd + d0];
                float vx = d.x + bb.x, vy = d.y + bb.y;
                float vz = d.z + bb.x, vw = d.w + bb.y;
                float px = __shfl_xor_sync(0xFFFFFFFFu, vx, 4);
                float py = __shfl_xor_sync(0xFFFFFFFFu, vy, 4);
                float pz = __shfl_xor_sync(0xFFFFFFFFu, vz, 4);
                float pw = __shfl_xor_sync(0xFFFFFFFFu, vw, 4);
                if (!(grp & 1)) {
                    int r0  = mt * 16 + grp;
                    int j2a = r0 >> 1, j2b = j2a + 4;
                    vf[d0 * VF_S + j2a]       = pkbf(vx, px);
                    vf[(d0 + 1) * VF_S + j2a] = pkbf(vy, py);
                    vf[d0 * VF_S + j2b]       = pkbf(vz, pz);
                    vf[(d0 + 1) * VF_S + j2b] = pkbf(vw, pw);
                }
            }
        }
        __syncthreads();   // QF/KF/VF visible; c1b reads complete
        // prefetch c0(h+1) into freed c1b (hidden behind scores/z/W1)
        if (h + 1 < NHEAD) {
            const uint4* src = wpf4 + (h + 1) * 3072;
#pragma unroll
            for (int i = 0; i < 6; i++)
                CPA16(smu + ((c1b + (t + i * 256) * 4) << 2), src + t + i * 256);
        }
        CPCOMMIT();        // unconditional (empty at h=7) keeps ladder uniform

        // ---- scores + softmax + z: half=0 warps only ----
        if (half == 0) {
            float4 Ds[8];
#pragma unroll
            for (int i = 0; i < 8; i++) Ds[i] = make_float4(0.f, 0.f, 0.f, 0.f);
#pragma unroll
            for (int ks = 0; ks < 2; ks++) {
                uint4 qa = ((const uint4*)(smw + QF_W))[(mt * 2 + ks) * 32 + lane];
#pragma unroll
                for (int ntp = 0; ntp < 4; ntp++) {
                    uint4 kb = ((const uint4*)(smw + KF_W))[(ks * 4 + ntp) * 32 + lane];
                    mma_bf16(Ds[2*ntp],   qa.x, qa.y, qa.z, qa.w, kb.x, kb.y);
                    mma_bf16(Ds[2*ntp+1], qa.x, qa.y, qa.z, qa.w, kb.z, kb.w);
                }
            }
            float m0 = Ds[0].x, m1 = Ds[0].z;
#pragma unroll
            for (int nt = 0; nt < 8; nt++) {
                m0 = fmaxf(m0, fmaxf(Ds[nt].x, Ds[nt].y));
                m1 = fmaxf(m1, fmaxf(Ds[nt].z, Ds[nt].w));
            }
            m0 = fmaxf(m0, __shfl_xor_sync(0xFFFFFFFFu, m0, 1));
            m0 = fmaxf(m0, __shfl_xor_sync(0xFFFFFFFFu, m0, 2));
            m1 = fmaxf(m1, __shfl_xor_sync(0xFFFFFFFFu, m1, 1));
            m1 = fmaxf(m1, __shfl_xor_sync(0xFFFFFFFFu, m1, 2));
            float s0 = 0.f, s1 = 0.f;
#pragma unroll
            for (int nt = 0; nt < 8; nt++) {
                Ds[nt].x = __expf(Ds[nt].x - m0);
                Ds[nt].y = __expf(Ds[nt].y - m0);
                Ds[nt].z = __expf(Ds[nt].z - m1);
                Ds[nt].w = __expf(Ds[nt].w - m1);
                s0 += Ds[nt].x + Ds[nt].y;
                s1 += Ds[nt].z + Ds[nt].w;
            }
            s0 += __shfl_xor_sync(0xFFFFFFFFu, s0, 1);
            s0 += __shfl_xor_sync(0xFFFFFFFFu, s0, 2);
            s1 += __shfl_xor_sync(0xFFFFFFFFu, s1, 1);
            s1 += __shfl_xor_sync(0xFFFFFFFFu, s1, 2);
            const float inv0 = 1.f / s0, inv1 = 1.f / s1;

            float4 Dz[4];
#pragma unroll
            for (int i = 0; i < 4; i++) Dz[i] = make_float4(0.f, 0.f, 0.f, 0.f);
            const uint32_t* vfw = smw + VF_W;
#pragma unroll
            for (int kz = 0; kz < 4; kz++) {
                uint32_t a0 = pkbf(Ds[2*kz].x   * inv0, Ds[2*kz].y   * inv0);
                uint32_t a1 = pkbf(Ds[2*kz].z   * inv1, Ds[2*kz].w   * inv1);
                uint32_t a2 = pkbf(Ds[2*kz+1].x * inv0, Ds[2*kz+1].y * inv0);
                uint32_t a3 = pkbf(Ds[2*kz+1].z * inv1, Ds[2*kz+1].w * inv1);
#pragma unroll
                for (int ntd = 0; ntd < 4; ntd++) {
                    uint32_t b0 = vfw[(ntd * 8 + grp) * VF_S + 8 * kz + tig];
                    uint32_t b1 = vfw[(ntd * 8 + grp) * VF_S + 8 * kz + tig + 4];
                    mma_bf16(Dz[ntd], a0, a1, a2, a3, b0, b1);
                }
            }
            // publish z -> ZA (alias c0b + 4096; disjoint from W1 copy at +0)
#pragma unroll
            for (int ks = 0; ks < 2; ks++) {
                uint4 za;
                za.x = pkbf(Dz[2*ks].x,   Dz[2*ks].y);
                za.y = pkbf(Dz[2*ks].z,   Dz[2*ks].w);
                za.z = pkbf(Dz[2*ks+1].x, Dz[2*ks+1].y);
                za.w = pkbf(Dz[2*ks+1].z, Dz[2*ks+1].w);
                ((uint4*)(smw + c0b + 4096))[(mt * 2 + ks) * 32 + lane] = za;
            }
        }
        CPWAIT1();         // W1(h) staged (c0(h+1) prefetch may pend)
        __syncthreads();   // WA + ZA visible to all

        // ---- facc += z @ W1 (WA = c0b, ZA = c0b+4096) ----
        {
            uint4 za0 = ((const uint4*)(smw + c0b + 4096))[(mt * 2 + 0) * 32 + lane];
            uint4 za1 = ((const uint4*)(smw + c0b + 4096))[(mt * 2 + 1) * 32 + lane];
            const uint4* wa4 = (const uint4*)(smw + c0b);
#pragma unroll
            for (int nc = 0; nc < 2; nc++) {
#pragma unroll
                for (int ks = 0; ks < 2; ks++) {
                    uint4 za = ks ? za1 : za0;
                    const uint4* bp = wa4 + (((nc * 2 + ks) * 8) + half * 4) * 32 + lane;
#pragma unroll
                    for (int jj = 0; jj < 4; jj++) {
                        uint4 bb = bp[jj * 32];
                        mma_bf16(facc4[nc*8 + 2*jj],   za.x, za.y, za.z, za.w, bb.x, bb.y);
                        mma_bf16(facc4[nc*8 + 2*jj+1], za.x, za.y, za.z, za.w, bb.z, bb.w);
                    }
                }
            }
        }
        // loop-top sync protects c1b(h) (= WA/ZA of h+1? no — c0b swap) reuse
    }

    // ===== epilogue: f = relu(facc + b1 + x); dot W2 (x exact from gmem) ====
    {
        const int r0 = mt * 16 + grp, r1 = r0 + 8;
        float part = 0.f;
#pragma unroll
        for (int fi = 0; fi < 16; fi++) {
            int nc = fi >> 3, nt = fi & 7;
            int n  = nc * 128 + half * 64 + nt * 8 + 2 * tig;
            float2 b1v = *(const float2*)&b1[n];
            float2 x0  = *(const float2*)&xg[r0 * DIM + n];
            float2 x1  = *(const float2*)&xg[r1 * DIM + n];
            float2 w20 = *(const float2*)&W2[r0 * DIM + n];
            float2 w21 = *(const float2*)&W2[r1 * DIM + n];
            float4 d = facc4[fi];
            float f0 = fmaxf(d.x + b1v.x + x0.x, 0.f);
            float f1 = fmaxf(d.y + b1v.y + x0.y, 0.f);
            float f2 = fmaxf(d.z + b1v.x + x1.x, 0.f);
            float f3 = fmaxf(d.w + b1v.y + x1.y, 0.f);
            part += f0 * w20.x + f1 * w20.y + f2 * w21.x + f3 * w21.y;
        }
        red[t] = part;
    }
    __syncthreads();

#pragma unroll
    for (int s = 128; s > 0; s >>= 1) {
        if (t < s) red[t] += red[t + s];
        __syncthreads();
    }
    if (t == 0) {
        out[b] = 1.f / (1.f + __expf(-(red[0] + b2[0])));
    }
}

extern "C" void kernel_launch(void* const* d_in, const int* in_sizes, int n_in,
                              void* d_out, int out_size)
{
    const float* x  = (const float*)d_in[0];
    const float* Wq = (const float*)d_in[1];
    const float* bq = (const float*)d_in[2];
    const float* Wk = (const float*)d_in[3];
    const float* bk = (const float*)d_in[4];
    const float* Wv = (const float*)d_in[5];
    const float* bv = (const float*)d_in[6];
    const float* W1 = (const float*)d_in[7];
    const float* b1 = (const float*)d_in[8];
    const float* W2 = (const float*)d_in[9];
    const float* b2 = (const float*)d_in[10];
    float* out = (float*)d_out;

    prep_kernel<<<128, 256>>>(Wq, Wk, Wv, W1);

    const int smem_bytes = SMEM_WORDS * 4;   // 95,744 B -> 2 CTAs/SM
    cudaFuncSetAttribute(autoint_kernel,
                         cudaFuncAttributeMaxDynamicSharedMemorySize, smem_bytes);
    autoint_kernel<<<8192, 256, smem_bytes>>>(x, bq, bk, bv, b1, W2, b2, out);
}